// round 16
// baseline (speedup 1.0000x reference)
#include <cuda_runtime.h>
#include <cuda_bf16.h>
#include <cstdint>

#define Bsz 8
#define Nn 2048
#define Fd 256
#define KC 32
#define NIT (Nn / KC)   // 64 chunks per pass

// -------- device scratch (no allocation allowed) --------
__device__ float g_Wh[(size_t)Bsz * Nn * Fd];      // Y1 spill scratch only
__device__ float g_S1[Bsz * Nn];
__device__ float g_S2[Bsz * Nn];
__device__ float g_E1p[Bsz * Nn];
__device__ float g_E1n[Bsz * Nn];
__device__ float g_E2p[Bsz * Nn];
__device__ float g_E2n[Bsz * Nn];
__device__ float g_Z1[Bsz * Nn];
__device__ float g_Z2[Bsz * Nn];
// X arrays, layout [b][j][f], bf16
__device__ unsigned short g_X1h[(size_t)Bsz * Nn * Fd];
__device__ unsigned short g_X1l[(size_t)Bsz * Nn * Fd];
__device__ unsigned short g_X2h[(size_t)Bsz * Nn * Fd];
__device__ unsigned short g_X2l[(size_t)Bsz * Nn * Fd];
// packed bit masks: [row][64] u32; word w = s*4+t holds bit l = mask at
// j = s*128 + 4*l + t
__device__ uint32_t g_M1[(size_t)Bsz * Nn * 64];
__device__ uint32_t g_M2[(size_t)Bsz * Nn * 64];

// -------- helpers --------
__device__ __forceinline__ uint32_t smem_u32(const void* p) {
    uint32_t a;
    asm("{ .reg .u64 t; cvta.to.shared.u64 t, %1; cvt.u32.u64 %0, t; }" : "=r"(a) : "l"(p));
    return a;
}
__device__ __forceinline__ void cp_async16(uint32_t dst, const void* src) {
    asm volatile("cp.async.cg.shared.global [%0], [%1], 16;" :: "r"(dst), "l"(src) : "memory");
}
__device__ __forceinline__ void cp_commit() {
    asm volatile("cp.async.commit_group;" ::: "memory");
}
__device__ __forceinline__ void cp_wait1() {
    asm volatile("cp.async.wait_group 1;" ::: "memory");
}
__device__ __forceinline__ void ldsm4(uint32_t* r, uint32_t addr) {
    asm volatile("ldmatrix.sync.aligned.m8n8.x4.shared.b16 {%0,%1,%2,%3}, [%4];"
                 : "=r"(r[0]), "=r"(r[1]), "=r"(r[2]), "=r"(r[3]) : "r"(addr));
}
__device__ __forceinline__ void ldsm4t(uint32_t* r, uint32_t addr) {
    asm volatile("ldmatrix.sync.aligned.m8n8.x4.trans.shared.b16 {%0,%1,%2,%3}, [%4];"
                 : "=r"(r[0]), "=r"(r[1]), "=r"(r[2]), "=r"(r[3]) : "r"(addr));
}
__device__ __forceinline__ void mma16816(float* d, const uint32_t* a, uint32_t b0, uint32_t b1) {
    asm volatile(
        "mma.sync.aligned.m16n8k16.row.col.f32.bf16.bf16.f32 "
        "{%0,%1,%2,%3}, {%4,%5,%6,%7}, {%8,%9}, {%0,%1,%2,%3};"
        : "+f"(d[0]), "+f"(d[1]), "+f"(d[2]), "+f"(d[3])
        : "r"(a[0]), "r"(a[1]), "r"(a[2]), "r"(a[3]), "r"(b0), "r"(b1));
}
__device__ __forceinline__ uint32_t bf16pair(float lo, float hi) {
    uint32_t r;
    asm("cvt.rn.bf16x2.f32 %0, %1, %2;" : "=r"(r) : "f"(hi), "f"(lo));
    return r;
}
__device__ __forceinline__ void split2(float f0, float f1, uint32_t& hi, uint32_t& lo) {
    float h0 = __bfloat162float(__float2bfloat16(f0));
    float h1 = __bfloat162float(__float2bfloat16(f1));
    hi = bf16pair(h0, h1);
    lo = bf16pair(f0 - h0, f1 - h1);
}
#define STS128(addr, w0, w1, w2, w3) \
    asm volatile("st.shared.v4.b32 [%0], {%1,%2,%3,%4};" \
                 :: "r"(addr), "r"(w0), "r"(w1), "r"(w2), "r"(w3) : "memory")

// ---------------------------------------------------------------------------
// K1: FUSED  Wh = h@W (HMMA, hi/lo split)  ->  s1,s2,exps  ->  X1/X2 splits
//     CTA: 128 rows x 256 f, 512 threads; Wh never written to DRAM.
//     X writes staged through SMEM for full coalescing.
// ---------------------------------------------------------------------------
#define G1_BUF 53248
#define G1_AL 10240
#define G1_BH 20480
#define G1_DYN (2 * G1_BUF)    // 106496
#define XT_OFF 8192            // u32 tile [128][132] at byte offset 8192
#define XT_STRIDE 132          // words per row (conflict-free)

__global__ void __launch_bounds__(512, 1)
gemm1_kernel(const float* __restrict__ h, const float* __restrict__ W,
             const float* __restrict__ a) {
    extern __shared__ char dynG[];
    const int tid = threadIdx.x;
    const int lane = tid & 31;
    const int wid = tid >> 5;
    const int wm = wid >> 2, wn = wid & 3;
    const size_t i0 = (size_t)blockIdx.x * 128;

    const uint32_t smem = smem_u32(dynG);

    const uint32_t aRowOff = (uint32_t)((32 * wm + ((lane >> 3) & 1) * 8 + (lane & 7)) * 80
                                        + (lane >> 4) * 16);
    const int jb = ((lane >> 3) & 1) * 8 + (lane & 7);
    const int ub = 8 * wn + (lane >> 4);
    const int jsw = jb & 7;

    const int ai = tid >> 2;
    const int amq = tid & 3;
    const int j0 = tid >> 5, u0 = tid & 31;
    const int j1 = (tid + 512) >> 5, u1 = tid & 31;

    float dacc[2][8][4];
#pragma unroll
    for (int mt = 0; mt < 2; mt++)
#pragma unroll
        for (int n8 = 0; n8 < 8; n8++)
#pragma unroll
            for (int k = 0; k < 4; k++) dacc[mt][n8][k] = 0.f;

    float4 ha0, ha1, w0a, w0b, w1a, w1b;
    auto load_regs = [&](int c) {
        const float* hp = h + (i0 + ai) * 256 + c * 32 + amq * 8;
        ha0 = ((const float4*)hp)[0];
        ha1 = ((const float4*)hp)[1];
        const float* wp0 = W + (size_t)(c * 32 + j0) * 256 + u0 * 8;
        w0a = ((const float4*)wp0)[0];
        w0b = ((const float4*)wp0)[1];
        const float* wp1 = W + (size_t)(c * 32 + j1) * 256 + u1 * 8;
        w1a = ((const float4*)wp1)[0];
        w1b = ((const float4*)wp1)[1];
    };

    load_regs(0);

#pragma unroll 1
    for (int c = 0; c < 8; c++) {
        const uint32_t base = smem + (uint32_t)(c & 1) * G1_BUF;
        {
            uint32_t hi[4], lo[4];
            split2(ha0.x, ha0.y, hi[0], lo[0]);
            split2(ha0.z, ha0.w, hi[1], lo[1]);
            split2(ha1.x, ha1.y, hi[2], lo[2]);
            split2(ha1.z, ha1.w, hi[3], lo[3]);
            uint32_t ad = base + (uint32_t)(ai * 80 + amq * 16);
            STS128(ad, hi[0], hi[1], hi[2], hi[3]);
            STS128(ad + G1_AL, lo[0], lo[1], lo[2], lo[3]);
        }
        {
            uint32_t hi[4], lo[4];
            split2(w0a.x, w0a.y, hi[0], lo[0]);
            split2(w0a.z, w0a.w, hi[1], lo[1]);
            split2(w0b.x, w0b.y, hi[2], lo[2]);
            split2(w0b.z, w0b.w, hi[3], lo[3]);
            uint32_t bd = base + G1_BH + (uint32_t)(j0 * 512 + ((u0 ^ (j0 & 7)) << 4));
            STS128(bd, hi[0], hi[1], hi[2], hi[3]);
            STS128(bd + 16384, lo[0], lo[1], lo[2], lo[3]);
            split2(w1a.x, w1a.y, hi[0], lo[0]);
            split2(w1a.z, w1a.w, hi[1], lo[1]);
            split2(w1b.x, w1b.y, hi[2], lo[2]);
            split2(w1b.z, w1b.w, hi[3], lo[3]);
            bd = base + G1_BH + (uint32_t)(j1 * 512 + ((u1 ^ (j1 & 7)) << 4));
            STS128(bd, hi[0], hi[1], hi[2], hi[3]);
            STS128(bd + 16384, lo[0], lo[1], lo[2], lo[3]);
        }
        __syncthreads();
        if (c < 7) load_regs(c + 1);

#pragma unroll
        for (int ks = 0; ks < 2; ks++) {
            uint32_t ah0[4], ah1[4], al0[4], al1[4];
            ldsm4(ah0, base + aRowOff + ks * 32);
            ldsm4(ah1, base + aRowOff + 16 * 80 + ks * 32);
            ldsm4(al0, base + G1_AL + aRowOff + ks * 32);
            ldsm4(al1, base + G1_AL + aRowOff + 16 * 80 + ks * 32);
            const int j = jb + ks * 16;
            const uint32_t rowb = base + G1_BH + j * 512;
#pragma unroll
            for (int ng = 0; ng < 4; ng++) {
                const int u = ub + 2 * ng;
                const uint32_t addr = rowb + ((u ^ jsw) << 4);
                uint32_t bh[4], bl[4];
                ldsm4t(bh, addr);
                ldsm4t(bl, addr + 16384);
                mma16816(dacc[0][2 * ng],     ah0, bh[0], bh[1]);
                mma16816(dacc[0][2 * ng + 1], ah0, bh[2], bh[3]);
                mma16816(dacc[1][2 * ng],     ah1, bh[0], bh[1]);
                mma16816(dacc[1][2 * ng + 1], ah1, bh[2], bh[3]);
                mma16816(dacc[0][2 * ng],     ah0, bl[0], bl[1]);
                mma16816(dacc[0][2 * ng + 1], ah0, bl[2], bl[3]);
                mma16816(dacc[1][2 * ng],     ah1, bl[0], bl[1]);
                mma16816(dacc[1][2 * ng + 1], ah1, bl[2], bl[3]);
                mma16816(dacc[0][2 * ng],     al0, bh[0], bh[1]);
                mma16816(dacc[0][2 * ng + 1], al0, bh[2], bh[3]);
                mma16816(dacc[1][2 * ng],     al1, bh[0], bh[1]);
                mma16816(dacc[1][2 * ng + 1], al1, bh[2], bh[3]);
            }
        }
    }
    __syncthreads();   // staging buffers dead; reuse dynG

    const int r0 = 32 * wm + (lane >> 2);
    const int cb = 64 * wn + (lane & 3) * 2;

    // ---- fused scores: s1/s2 per row from accumulators ----
    float* sred = (float*)dynG;              // [128][8]  (bytes 0..4095)
    float* a_s  = (float*)(dynG + 4096);     // 512 floats (4096..6143)
    float* e2ps = (float*)(dynG + 6144);     // 128
    float* e2ns = (float*)(dynG + 6656);     // 128  (ends 7168 < XT_OFF)
    if (tid < 512) a_s[tid] = a[tid];
    __syncthreads();

    float p1[2][2] = {{0.f, 0.f}, {0.f, 0.f}};
    float p2[2][2] = {{0.f, 0.f}, {0.f, 0.f}};
#pragma unroll
    for (int mt = 0; mt < 2; mt++)
#pragma unroll
        for (int n8 = 0; n8 < 8; n8++) {
            int c = cb + 8 * n8;
            float a1x = a_s[c], a1y = a_s[c + 1];
            float a2x = a_s[256 + c], a2y = a_s[256 + c + 1];
            p1[mt][0] += dacc[mt][n8][0] * a1x + dacc[mt][n8][1] * a1y;
            p2[mt][0] += dacc[mt][n8][0] * a2x + dacc[mt][n8][1] * a2y;
            p1[mt][1] += dacc[mt][n8][2] * a1x + dacc[mt][n8][3] * a1y;
            p2[mt][1] += dacc[mt][n8][2] * a2x + dacc[mt][n8][3] * a2y;
        }
#pragma unroll
    for (int mt = 0; mt < 2; mt++)
#pragma unroll
        for (int fr = 0; fr < 2; fr++) {
            p1[mt][fr] += __shfl_xor_sync(0xffffffffu, p1[mt][fr], 1);
            p1[mt][fr] += __shfl_xor_sync(0xffffffffu, p1[mt][fr], 2);
            p2[mt][fr] += __shfl_xor_sync(0xffffffffu, p2[mt][fr], 1);
            p2[mt][fr] += __shfl_xor_sync(0xffffffffu, p2[mt][fr], 2);
        }
    if ((lane & 3) == 0) {
#pragma unroll
        for (int mt = 0; mt < 2; mt++)
#pragma unroll
            for (int fr = 0; fr < 2; fr++) {
                int row = r0 + 16 * mt + 8 * fr;
                sred[row * 8 + wn] = p1[mt][fr];
                sred[row * 8 + 4 + wn] = p2[mt][fr];
            }
    }
    __syncthreads();
    if (tid < 128) {
        int row = tid;
        float s1 = sred[row * 8] + sred[row * 8 + 1] + sred[row * 8 + 2] + sred[row * 8 + 3];
        float s2 = sred[row * 8 + 4] + sred[row * 8 + 5] + sred[row * 8 + 6] + sred[row * 8 + 7];
        size_t gr = i0 + row;
        g_S1[gr] = s1; g_S2[gr] = s2;
        g_E1p[gr] = expf(s1);  g_E1n[gr] = expf(0.2f * s1);
        float ep = expf(s2), en = expf(0.2f * s2);
        g_E2p[gr] = ep; g_E2n[gr] = en;
        e2ps[row] = ep; e2ns[row] = en;
    }
    __syncthreads();

    // ---- fused buildX with SMEM transpose staging (coalesced writes) ----
    uint32_t* xt = (uint32_t*)(dynG + XT_OFF);   // [128][132] u32
    unsigned short* dsts[4] = {g_X1h, g_X1l, g_X2h, g_X2l};

#pragma unroll 1
    for (int arr = 0; arr < 4; arr++) {
        const bool isX1 = (arr < 2);
        const bool isHi = ((arr & 1) == 0);
        // stage: fragment -> tile
#pragma unroll
        for (int mt = 0; mt < 2; mt++) {
            int ra = r0 + 16 * mt;
            float sa = isX1 ? e2ps[ra] : e2ns[ra];
            float sb = isX1 ? e2ps[ra + 8] : e2ns[ra + 8];
#pragma unroll
            for (int n8 = 0; n8 < 8; n8++) {
                int wcol = cb / 2 + 4 * n8;
                uint32_t hi, lo;
                split2(dacc[mt][n8][0] * sa, dacc[mt][n8][1] * sa, hi, lo);
                xt[ra * XT_STRIDE + wcol] = isHi ? hi : lo;
                split2(dacc[mt][n8][2] * sb, dacc[mt][n8][3] * sb, hi, lo);
                xt[(ra + 8) * XT_STRIDE + wcol] = isHi ? hi : lo;
            }
        }
        __syncthreads();
        // drain: tile -> global, fully coalesced uint4
        unsigned short* dst = dsts[arr];
#pragma unroll
        for (int r = 0; r < 8; r++) {
            int idx = tid + r * 512;
            int row = idx >> 5;
            int c4 = (idx & 31) * 4;
            uint32_t w0 = xt[row * XT_STRIDE + c4];
            uint32_t w1 = xt[row * XT_STRIDE + c4 + 1];
            uint32_t w2 = xt[row * XT_STRIDE + c4 + 2];
            uint32_t w3 = xt[row * XT_STRIDE + c4 + 3];
            *(uint4*)&dst[(i0 + row) * 256 + c4 * 2] = make_uint4(w0, w1, w2, w3);
        }
        __syncthreads();
    }
}

// ---------------------------------------------------------------------------
// K2: packed bit masks + Z sums (R13-proven coalesced ballot)
// ---------------------------------------------------------------------------
__global__ __launch_bounds__(256) void mask_kernel(const float* __restrict__ adj) {
    int row = blockIdx.x * 8 + (threadIdx.x >> 5);
    int lane = threadIdx.x & 31;
    int b = row >> 11;
    const float4* ar  = (const float4*)(adj + (size_t)row * Nn);
    const float4* s2g = (const float4*)(g_S2 + b * Nn);
    const float4* epg = (const float4*)(g_E2p + b * Nn);
    const float4* eng = (const float4*)(g_E2n + b * Nn);
    float ns1 = -g_S1[row];
    float z1 = 0.f, z2 = 0.f;
    uint32_t w1lo = 0, w1hi = 0, w2lo = 0, w2hi = 0;
#pragma unroll 2
    for (int s = 0; s < 16; s++) {
        int q = s * 32 + lane;
        float4 av = ar[q];
        float4 sv = s2g[q];
        float4 pv = epg[q];
        float4 nv = eng[q];
        float avv[4] = {av.x, av.y, av.z, av.w};
        float svv[4] = {sv.x, sv.y, sv.z, sv.w};
        float pvv[4] = {pv.x, pv.y, pv.z, pv.w};
        float nvv[4] = {nv.x, nv.y, nv.z, nv.w};
        bool m1[4], m2[4];
#pragma unroll
        for (int t = 0; t < 4; t++) {
            bool on = avv[t] > 0.5f;
            bool pos = svv[t] > ns1;
            m1[t] = on && pos;
            m2[t] = on && !pos;
            if (m1[t]) z1 += pvv[t];
            if (m2[t]) z2 += nvv[t];
        }
#pragma unroll
        for (int t = 0; t < 4; t++) {
            uint32_t b1 = __ballot_sync(0xffffffffu, m1[t]);
            uint32_t b2 = __ballot_sync(0xffffffffu, m2[t]);
            int w = s * 4 + t;
            if (lane == (w & 31)) {
                if (w < 32) { w1lo = b1; w2lo = b2; }
                else        { w1hi = b1; w2hi = b2; }
            }
        }
    }
#pragma unroll
    for (int o = 16; o; o >>= 1) {
        z1 += __shfl_xor_sync(0xffffffffu, z1, o);
        z2 += __shfl_xor_sync(0xffffffffu, z2, o);
    }
    g_M1[(size_t)row * 64 + lane] = w1lo;
    g_M1[(size_t)row * 64 + 32 + lane] = w1hi;
    g_M2[(size_t)row * 64 + lane] = w2lo;
    g_M2[(size_t)row * 64 + 32 + lane] = w2hi;
    if (lane == 0) { g_Z1[row] = z1; g_Z2[row] = z2; }
}

// ---------------------------------------------------------------------------
// K3: HMMA masked attention + LayerNorm + exact GELU (R13-proven, unchanged)
// ---------------------------------------------------------------------------
#define ROWS 128
#define XS_STRIDE 260
#define SLOT_BYTES 32768
#define MEXP0 (3 * SLOT_BYTES)
#define MSTRIDE 80
#define MEXP1 (MEXP0 + ROWS * MSTRIDE)
#define PACKED_OFF (MEXP1 + ROWS * MSTRIDE)
#define DYN_B (PACKED_OFF + 32768)

__global__ void __launch_bounds__(512, 1)
attn_mma_kernel(const float* __restrict__ gamma, const float* __restrict__ beta,
                float* __restrict__ out) {
    extern __shared__ char dyn[];
    __shared__ float e1p_s[ROWS], e1n_s[ROWS], invz_s[ROWS], mu_s[ROWS], rs_s[ROWS];

    const int tid = threadIdx.x;
    const int lane = tid & 31;
    const int wid = tid >> 5;
    const int wm = wid >> 2, wn = wid & 3;
    const int b = blockIdx.y;
    const int i0 = blockIdx.x * ROWS;

    const uint32_t smem = smem_u32(dyn);
    float* xs = (float*)dyn;
    uint32_t* packed_s = (uint32_t*)(dyn + PACKED_OFF);

    if (tid < ROWS) {
        float e1p = g_E1p[b * Nn + i0 + tid];
        float e1n = g_E1n[b * Nn + i0 + tid];
        e1p_s[tid] = e1p;
        e1n_s[tid] = e1n;
        invz_s[tid] = 1.f / (e1p * g_Z1[b * Nn + i0 + tid] +
                             e1n * g_Z2[b * Nn + i0 + tid]);
    }

    const uint32_t aRowOff = (uint32_t)((32 * wm + ((lane >> 3) & 1) * 8 + (lane & 7)) * MSTRIDE
                                        + (lane >> 4) * 16);
    const int jb = ((lane >> 3) & 1) * 8 + (lane & 7);
    const int ub = 8 * wn + (lane >> 4);
    const int jsw = jb & 7;

    const int mi = tid >> 2;
    const int mq = tid & 3;
    const uint32_t mstRel = (uint32_t)(mi * MSTRIDE + mq * 16);

    const int r0 = 32 * wm + (lane >> 2);
    const int cb = 64 * wn + (lane & 3) * 2;
    float* gy = g_Wh + ((size_t)b * Nn + i0) * Fd;

    float dacc[2][8][4];

#pragma unroll 1
    for (int pass = 0; pass < 2; pass++) {
        const unsigned short* srcH =
            (pass == 0 ? g_X1h : g_X2h) + (size_t)b * Nn * Fd;
        const unsigned short* srcL =
            (pass == 0 ? g_X1l : g_X2l) + (size_t)b * Nn * Fd;
        const uint32_t* gM =
            (pass == 0 ? g_M1 : g_M2) + (size_t)(b * Nn + i0) * 64;

#pragma unroll
        for (int mt = 0; mt < 2; mt++)
#pragma unroll
            for (int n8 = 0; n8 < 8; n8++)
#pragma unroll
                for (int k = 0; k < 4; k++) dacc[mt][n8][k] = 0.f;

#pragma unroll
        for (int r = 0; r < 4; r++) {
            int idx = tid + r * 512;
            *(uint4*)&packed_s[idx * 4] = ((const uint4*)gM)[idx];
        }

        // prologue: issue chunks 0,1
#pragma unroll
        for (int c0 = 0; c0 < 2; c0++) {
            uint32_t dst = smem + (uint32_t)c0 * SLOT_BYTES;
            size_t grow = (size_t)(c0 * KC) * Fd;
#pragma unroll
            for (int r = 0; r < 2; r++) {
                int e = tid + r * 512;
                int j = e >> 5, u = e & 31;
                uint32_t d = dst + j * 512 + ((u ^ (j & 7)) << 4);
                cp_async16(d, srcH + grow + (size_t)j * Fd + u * 8);
                cp_async16(d + 16384, srcL + grow + (size_t)j * Fd + u * 8);
            }
            cp_commit();
        }
        __syncthreads();

        // expand mask chunk 0 -> buf0
        {
            uint4 wv = *(const uint4*)&packed_s[mi * 64];
            uint32_t sh = (uint32_t)(mq << 1);
            uint32_t w0 = ((wv.x >> sh) & 1u) * 0x3F80u + ((wv.y >> sh) & 1u) * 0x3F800000u;
            uint32_t w1 = ((wv.z >> sh) & 1u) * 0x3F80u + ((wv.w >> sh) & 1u) * 0x3F800000u;
            uint32_t w2 = ((wv.x >> (sh + 1)) & 1u) * 0x3F80u + ((wv.y >> (sh + 1)) & 1u) * 0x3F800000u;
            uint32_t w3 = ((wv.z >> (sh + 1)) & 1u) * 0x3F80u + ((wv.w >> (sh + 1)) & 1u) * 0x3F800000u;
            STS128(smem + MEXP0 + mstRel, w0, w1, w2, w3);
        }

#pragma unroll 1
        for (int it = 0; it < NIT; it++) {
            cp_wait1();
            __syncthreads();

            {
                int c2 = it + 2;
                if (c2 < NIT) {
                    int s2 = c2 % 3;
                    uint32_t dst = smem + (uint32_t)s2 * SLOT_BYTES;
                    size_t grow = (size_t)(c2 * KC) * Fd;
#pragma unroll
                    for (int r = 0; r < 2; r++) {
                        int e = tid + r * 512;
                        int j = e >> 5, u = e & 31;
                        uint32_t d = dst + j * 512 + ((u ^ (j & 7)) << 4);
                        cp_async16(d, srcH + grow + (size_t)j * Fd + u * 8);
                        cp_async16(d + 16384, srcL + grow + (size_t)j * Fd + u * 8);
                    }
                }
                cp_commit();
            }

            const uint32_t xb = smem + (uint32_t)(it % 3) * SLOT_BYTES;
            const uint32_t mbuf = smem + ((it & 1) ? MEXP1 : MEXP0);
#pragma unroll
            for (int ks = 0; ks < 2; ks++) {
                uint32_t a0[4], a1[4];
                ldsm4(a0, mbuf + aRowOff + ks * 32);
                ldsm4(a1, mbuf + aRowOff + 16 * MSTRIDE + ks * 32);
                const int j = jb + ks * 16;
                const uint32_t rowb = xb + j * 512;
#pragma unroll
                for (int ng = 0; ng < 4; ng++) {
                    const int u = ub + 2 * ng;
                    const uint32_t addrH = rowb + ((u ^ jsw) << 4);
                    uint32_t bh[4], bl[4];
                    ldsm4t(bh, addrH);
                    ldsm4t(bl, addrH + 16384);
                    mma16816(dacc[0][2 * ng],     a0, bh[0], bh[1]);
                    mma16816(dacc[0][2 * ng + 1], a0, bh[2], bh[3]);
                    mma16816(dacc[1][2 * ng],     a1, bh[0], bh[1]);
                    mma16816(dacc[1][2 * ng + 1], a1, bh[2], bh[3]);
                    mma16816(dacc[0][2 * ng],     a0, bl[0], bl[1]);
                    mma16816(dacc[0][2 * ng + 1], a0, bl[2], bl[3]);
                    mma16816(dacc[1][2 * ng],     a1, bl[0], bl[1]);
                    mma16816(dacc[1][2 * ng + 1], a1, bl[2], bl[3]);
                }
            }

            if (it + 1 < NIT) {
                int cc = it + 1;
                uint4 wv = *(const uint4*)&packed_s[mi * 64 + ((cc >> 2) << 2)];
                uint32_t sh = (uint32_t)(((cc & 3) << 3) + (mq << 1));
                uint32_t w0 = ((wv.x >> sh) & 1u) * 0x3F80u + ((wv.y >> sh) & 1u) * 0x3F800000u;
                uint32_t w1 = ((wv.z >> sh) & 1u) * 0x3F80u + ((wv.w >> sh) & 1u) * 0x3F800000u;
                uint32_t w2 = ((wv.x >> (sh + 1)) & 1u) * 0x3F80u + ((wv.y >> (sh + 1)) & 1u) * 0x3F800000u;
                uint32_t w3 = ((wv.z >> (sh + 1)) & 1u) * 0x3F80u + ((wv.w >> (sh + 1)) & 1u) * 0x3F800000u;
                STS128(smem + ((cc & 1) ? MEXP1 : MEXP0) + mstRel, w0, w1, w2, w3);
            }
        }
        __syncthreads();

        if (pass == 0) {
#pragma unroll
            for (int mt = 0; mt < 2; mt++) {
                int ra = r0 + 16 * mt;
                float ea = e1p_s[ra], eb = e1p_s[ra + 8];
#pragma unroll
                for (int n8 = 0; n8 < 8; n8++) {
                    int c = cb + 8 * n8;
                    *(float2*)&gy[(size_t)ra * 256 + c] =
                        make_float2(ea * dacc[mt][n8][0], ea * dacc[mt][n8][1]);
                    *(float2*)&gy[(size_t)(ra + 8) * 256 + c] =
                        make_float2(eb * dacc[mt][n8][2], eb * dacc[mt][n8][3]);
                }
            }
        }
    }

#pragma unroll
    for (int mt = 0; mt < 2; mt++) {
        int ra = r0 + 16 * mt;
        float ea = e1n_s[ra], eb = e1n_s[ra + 8];
        float iza = invz_s[ra], izb = invz_s[ra + 8];
#pragma unroll
        for (int n8 = 0; n8 < 8; n8++) {
            int c = cb + 8 * n8;
            float2 ya = *(const float2*)&gy[(size_t)ra * 256 + c];
            float2 yb = *(const float2*)&gy[(size_t)(ra + 8) * 256 + c];
            xs[ra * XS_STRIDE + c]     = (ya.x + ea * dacc[mt][n8][0]) * iza;
            xs[ra * XS_STRIDE + c + 1] = (ya.y + ea * dacc[mt][n8][1]) * iza;
            xs[(ra + 8) * XS_STRIDE + c]     = (yb.x + eb * dacc[mt][n8][2]) * izb;
            xs[(ra + 8) * XS_STRIDE + c + 1] = (yb.y + eb * dacc[mt][n8][3]) * izb;
        }
    }
    __syncthreads();

    {
        int row = tid >> 2, q = tid & 3;
        const float4* xr = (const float4*)&xs[row * XS_STRIDE + q * 64];
        float sum = 0.f, ssq = 0.f;
#pragma unroll
        for (int k = 0; k < 16; k++) {
            float4 v = xr[k];
            sum += v.x + v.y + v.z + v.w;
            ssq += v.x * v.x + v.y * v.y + v.z * v.z + v.w * v.w;
        }
        sum += __shfl_xor_sync(0xffffffffu, sum, 1);
        sum += __shfl_xor_sync(0xffffffffu, sum, 2);
        ssq += __shfl_xor_sync(0xffffffffu, ssq, 1);
        ssq += __shfl_xor_sync(0xffffffffu, ssq, 2);
        if (q == 0) {
            float mu = sum * (1.f / 256.f);
            float var = fmaxf(ssq * (1.f / 256.f) - mu * mu, 0.f);
            mu_s[row] = mu;
            rs_s[row] = rsqrtf(var + 1e-5f);
        }
    }
    __syncthreads();

    float* outb = out + ((size_t)b * Nn + i0) * Fd;
#pragma unroll 1
    for (int r = 0; r < 16; r++) {
        int u = tid + r * 512;
        int i = u >> 6;
        int c4 = (u & 63) * 4;
        float mu = mu_s[i], rs = rs_s[i];
        float4 xv = *(const float4*)&xs[i * XS_STRIDE + c4];
        float4 g = *(const float4*)&gamma[c4];
        float4 be = *(const float4*)&beta[c4];
        float x[4] = {xv.x, xv.y, xv.z, xv.w};
        float gv[4] = {g.x, g.y, g.z, g.w};
        float bv[4] = {be.x, be.y, be.z, be.w};
        float ov[4];
#pragma unroll
        for (int e = 0; e < 4; e++) {
            float y = (x[e] - mu) * rs * gv[e] + bv[e];
            ov[e] = 0.5f * y * (1.f + erff(y * 0.7071067811865475f));
        }
        *(float4*)&outb[(size_t)i * 256 + c4] = make_float4(ov[0], ov[1], ov[2], ov[3]);
    }
}

// ---------------------------------------------------------------------------
extern "C" void kernel_launch(void* const* d_in, const int* in_sizes, int n_in,
                              void* d_out, int out_size) {
    const float* h     = (const float*)d_in[0];
    const float* adj   = (const float*)d_in[1];
    const float* W     = (const float*)d_in[2];
    const float* a     = (const float*)d_in[3];
    const float* gamma = (const float*)d_in[4];
    const float* beta  = (const float*)d_in[5];
    float* out = (float*)d_out;

    cudaFuncSetAttribute(gemm1_kernel,
                         cudaFuncAttributeMaxDynamicSharedMemorySize, G1_DYN);
    cudaFuncSetAttribute(attn_mma_kernel,
                         cudaFuncAttributeMaxDynamicSharedMemorySize, DYN_B);

    gemm1_kernel<<<128, 512, G1_DYN>>>(h, W, a);
    mask_kernel<<<2048, 256>>>(adj);
    attn_mma_kernel<<<dim3(16, 8), 512, DYN_B>>>(gamma, beta, out);
}

// round 17
// speedup vs baseline: 1.0393x; 1.0393x over previous
#include <cuda_runtime.h>
#include <cuda_bf16.h>
#include <cstdint>

#define Bsz 8
#define Nn 2048
#define Fd 256
#define KC 64
#define NIT (Nn / KC)   // 32 chunks per pass

// -------- device scratch (no allocation allowed) --------
__device__ float g_Wh[(size_t)Bsz * Nn * Fd];      // Y1 spill scratch only
__device__ float g_S1[Bsz * Nn];
__device__ float g_S2[Bsz * Nn];
__device__ float g_E1p[Bsz * Nn];
__device__ float g_E1n[Bsz * Nn];
__device__ float g_E2p[Bsz * Nn];
__device__ float g_E2n[Bsz * Nn];
__device__ float g_Z1[Bsz * Nn];
__device__ float g_Z2[Bsz * Nn];
// X arrays, layout [b][j][f], bf16
__device__ unsigned short g_X1h[(size_t)Bsz * Nn * Fd];
__device__ unsigned short g_X1l[(size_t)Bsz * Nn * Fd];
__device__ unsigned short g_X2h[(size_t)Bsz * Nn * Fd];
__device__ unsigned short g_X2l[(size_t)Bsz * Nn * Fd];
// packed bit masks, PLAIN layout: [row][64] u32; word w bit l = mask at j=w*32+l
__device__ uint32_t g_M1[(size_t)Bsz * Nn * 64];
__device__ uint32_t g_M2[(size_t)Bsz * Nn * 64];

// -------- helpers --------
__device__ __forceinline__ uint32_t smem_u32(const void* p) {
    uint32_t a;
    asm("{ .reg .u64 t; cvta.to.shared.u64 t, %1; cvt.u32.u64 %0, t; }" : "=r"(a) : "l"(p));
    return a;
}
__device__ __forceinline__ void cp_async16(uint32_t dst, const void* src) {
    asm volatile("cp.async.cg.shared.global [%0], [%1], 16;" :: "r"(dst), "l"(src) : "memory");
}
__device__ __forceinline__ void cp_commit() {
    asm volatile("cp.async.commit_group;" ::: "memory");
}
__device__ __forceinline__ void cp_wait0() {
    asm volatile("cp.async.wait_group 0;" ::: "memory");
}
__device__ __forceinline__ void ldsm4(uint32_t* r, uint32_t addr) {
    asm volatile("ldmatrix.sync.aligned.m8n8.x4.shared.b16 {%0,%1,%2,%3}, [%4];"
                 : "=r"(r[0]), "=r"(r[1]), "=r"(r[2]), "=r"(r[3]) : "r"(addr));
}
__device__ __forceinline__ void ldsm4t(uint32_t* r, uint32_t addr) {
    asm volatile("ldmatrix.sync.aligned.m8n8.x4.trans.shared.b16 {%0,%1,%2,%3}, [%4];"
                 : "=r"(r[0]), "=r"(r[1]), "=r"(r[2]), "=r"(r[3]) : "r"(addr));
}
__device__ __forceinline__ void mma16816(float* d, const uint32_t* a, uint32_t b0, uint32_t b1) {
    asm volatile(
        "mma.sync.aligned.m16n8k16.row.col.f32.bf16.bf16.f32 "
        "{%0,%1,%2,%3}, {%4,%5,%6,%7}, {%8,%9}, {%0,%1,%2,%3};"
        : "+f"(d[0]), "+f"(d[1]), "+f"(d[2]), "+f"(d[3])
        : "r"(a[0]), "r"(a[1]), "r"(a[2]), "r"(a[3]), "r"(b0), "r"(b1));
}
__device__ __forceinline__ uint32_t bf16pair(float lo, float hi) {
    uint32_t r;
    asm("cvt.rn.bf16x2.f32 %0, %1, %2;" : "=r"(r) : "f"(hi), "f"(lo));
    return r;
}
__device__ __forceinline__ void split2(float f0, float f1, uint32_t& hi, uint32_t& lo) {
    float h0 = __bfloat162float(__float2bfloat16(f0));
    float h1 = __bfloat162float(__float2bfloat16(f1));
    hi = bf16pair(h0, h1);
    lo = bf16pair(f0 - h0, f1 - h1);
}
#define STS128(addr, w0, w1, w2, w3) \
    asm volatile("st.shared.v4.b32 [%0], {%1,%2,%3,%4};" \
                 :: "r"(addr), "r"(w0), "r"(w1), "r"(w2), "r"(w3) : "memory")

// ---------------------------------------------------------------------------
// K1: FUSED  Wh = h@W (HMMA, hi/lo split) -> scores -> X splits (R16-proven)
// ---------------------------------------------------------------------------
#define G1_BUF 53248
#define G1_AL 10240
#define G1_BH 20480
#define G1_DYN (2 * G1_BUF)
#define XT_OFF 8192
#define XT_STRIDE 132

__global__ void __launch_bounds__(512, 1)
gemm1_kernel(const float* __restrict__ h, const float* __restrict__ W,
             const float* __restrict__ a) {
    extern __shared__ char dynG[];
    const int tid = threadIdx.x;
    const int lane = tid & 31;
    const int wid = tid >> 5;
    const int wm = wid >> 2, wn = wid & 3;
    const size_t i0 = (size_t)blockIdx.x * 128;

    const uint32_t smem = smem_u32(dynG);

    const uint32_t aRowOff = (uint32_t)((32 * wm + ((lane >> 3) & 1) * 8 + (lane & 7)) * 80
                                        + (lane >> 4) * 16);
    const int jb = ((lane >> 3) & 1) * 8 + (lane & 7);
    const int ub = 8 * wn + (lane >> 4);
    const int jsw = jb & 7;

    const int ai = tid >> 2;
    const int amq = tid & 3;
    const int j0 = tid >> 5, u0 = tid & 31;
    const int j1 = (tid + 512) >> 5, u1 = tid & 31;

    float dacc[2][8][4];
#pragma unroll
    for (int mt = 0; mt < 2; mt++)
#pragma unroll
        for (int n8 = 0; n8 < 8; n8++)
#pragma unroll
            for (int k = 0; k < 4; k++) dacc[mt][n8][k] = 0.f;

    float4 ha0, ha1, w0a, w0b, w1a, w1b;
    auto load_regs = [&](int c) {
        const float* hp = h + (i0 + ai) * 256 + c * 32 + amq * 8;
        ha0 = ((const float4*)hp)[0];
        ha1 = ((const float4*)hp)[1];
        const float* wp0 = W + (size_t)(c * 32 + j0) * 256 + u0 * 8;
        w0a = ((const float4*)wp0)[0];
        w0b = ((const float4*)wp0)[1];
        const float* wp1 = W + (size_t)(c * 32 + j1) * 256 + u1 * 8;
        w1a = ((const float4*)wp1)[0];
        w1b = ((const float4*)wp1)[1];
    };

    load_regs(0);

#pragma unroll 1
    for (int c = 0; c < 8; c++) {
        const uint32_t base = smem + (uint32_t)(c & 1) * G1_BUF;
        {
            uint32_t hi[4], lo[4];
            split2(ha0.x, ha0.y, hi[0], lo[0]);
            split2(ha0.z, ha0.w, hi[1], lo[1]);
            split2(ha1.x, ha1.y, hi[2], lo[2]);
            split2(ha1.z, ha1.w, hi[3], lo[3]);
            uint32_t ad = base + (uint32_t)(ai * 80 + amq * 16);
            STS128(ad, hi[0], hi[1], hi[2], hi[3]);
            STS128(ad + G1_AL, lo[0], lo[1], lo[2], lo[3]);
        }
        {
            uint32_t hi[4], lo[4];
            split2(w0a.x, w0a.y, hi[0], lo[0]);
            split2(w0a.z, w0a.w, hi[1], lo[1]);
            split2(w0b.x, w0b.y, hi[2], lo[2]);
            split2(w0b.z, w0b.w, hi[3], lo[3]);
            uint32_t bd = base + G1_BH + (uint32_t)(j0 * 512 + ((u0 ^ (j0 & 7)) << 4));
            STS128(bd, hi[0], hi[1], hi[2], hi[3]);
            STS128(bd + 16384, lo[0], lo[1], lo[2], lo[3]);
            split2(w1a.x, w1a.y, hi[0], lo[0]);
            split2(w1a.z, w1a.w, hi[1], lo[1]);
            split2(w1b.x, w1b.y, hi[2], lo[2]);
            split2(w1b.z, w1b.w, hi[3], lo[3]);
            bd = base + G1_BH + (uint32_t)(j1 * 512 + ((u1 ^ (j1 & 7)) << 4));
            STS128(bd, hi[0], hi[1], hi[2], hi[3]);
            STS128(bd + 16384, lo[0], lo[1], lo[2], lo[3]);
        }
        __syncthreads();
        if (c < 7) load_regs(c + 1);

#pragma unroll
        for (int ks = 0; ks < 2; ks++) {
            uint32_t ah0[4], ah1[4], al0[4], al1[4];
            ldsm4(ah0, base + aRowOff + ks * 32);
            ldsm4(ah1, base + aRowOff + 16 * 80 + ks * 32);
            ldsm4(al0, base + G1_AL + aRowOff + ks * 32);
            ldsm4(al1, base + G1_AL + aRowOff + 16 * 80 + ks * 32);
            const int j = jb + ks * 16;
            const uint32_t rowb = base + G1_BH + j * 512;
#pragma unroll
            for (int ng = 0; ng < 4; ng++) {
                const int u = ub + 2 * ng;
                const uint32_t addr = rowb + ((u ^ jsw) << 4);
                uint32_t bh[4], bl[4];
                ldsm4t(bh, addr);
                ldsm4t(bl, addr + 16384);
                mma16816(dacc[0][2 * ng],     ah0, bh[0], bh[1]);
                mma16816(dacc[0][2 * ng + 1], ah0, bh[2], bh[3]);
                mma16816(dacc[1][2 * ng],     ah1, bh[0], bh[1]);
                mma16816(dacc[1][2 * ng + 1], ah1, bh[2], bh[3]);
                mma16816(dacc[0][2 * ng],     ah0, bl[0], bl[1]);
                mma16816(dacc[0][2 * ng + 1], ah0, bl[2], bl[3]);
                mma16816(dacc[1][2 * ng],     ah1, bl[0], bl[1]);
                mma16816(dacc[1][2 * ng + 1], ah1, bl[2], bl[3]);
                mma16816(dacc[0][2 * ng],     al0, bh[0], bh[1]);
                mma16816(dacc[0][2 * ng + 1], al0, bh[2], bh[3]);
                mma16816(dacc[1][2 * ng],     al1, bh[0], bh[1]);
                mma16816(dacc[1][2 * ng + 1], al1, bh[2], bh[3]);
            }
        }
    }
    __syncthreads();

    const int r0 = 32 * wm + (lane >> 2);
    const int cb = 64 * wn + (lane & 3) * 2;

    float* sred = (float*)dynG;
    float* a_s  = (float*)(dynG + 4096);
    float* e2ps = (float*)(dynG + 6144);
    float* e2ns = (float*)(dynG + 6656);
    if (tid < 512) a_s[tid] = a[tid];
    __syncthreads();

    float p1[2][2] = {{0.f, 0.f}, {0.f, 0.f}};
    float p2[2][2] = {{0.f, 0.f}, {0.f, 0.f}};
#pragma unroll
    for (int mt = 0; mt < 2; mt++)
#pragma unroll
        for (int n8 = 0; n8 < 8; n8++) {
            int c = cb + 8 * n8;
            float a1x = a_s[c], a1y = a_s[c + 1];
            float a2x = a_s[256 + c], a2y = a_s[256 + c + 1];
            p1[mt][0] += dacc[mt][n8][0] * a1x + dacc[mt][n8][1] * a1y;
            p2[mt][0] += dacc[mt][n8][0] * a2x + dacc[mt][n8][1] * a2y;
            p1[mt][1] += dacc[mt][n8][2] * a1x + dacc[mt][n8][3] * a1y;
            p2[mt][1] += dacc[mt][n8][2] * a2x + dacc[mt][n8][3] * a2y;
        }
#pragma unroll
    for (int mt = 0; mt < 2; mt++)
#pragma unroll
        for (int fr = 0; fr < 2; fr++) {
            p1[mt][fr] += __shfl_xor_sync(0xffffffffu, p1[mt][fr], 1);
            p1[mt][fr] += __shfl_xor_sync(0xffffffffu, p1[mt][fr], 2);
            p2[mt][fr] += __shfl_xor_sync(0xffffffffu, p2[mt][fr], 1);
            p2[mt][fr] += __shfl_xor_sync(0xffffffffu, p2[mt][fr], 2);
        }
    if ((lane & 3) == 0) {
#pragma unroll
        for (int mt = 0; mt < 2; mt++)
#pragma unroll
            for (int fr = 0; fr < 2; fr++) {
                int row = r0 + 16 * mt + 8 * fr;
                sred[row * 8 + wn] = p1[mt][fr];
                sred[row * 8 + 4 + wn] = p2[mt][fr];
            }
    }
    __syncthreads();
    if (tid < 128) {
        int row = tid;
        float s1 = sred[row * 8] + sred[row * 8 + 1] + sred[row * 8 + 2] + sred[row * 8 + 3];
        float s2 = sred[row * 8 + 4] + sred[row * 8 + 5] + sred[row * 8 + 6] + sred[row * 8 + 7];
        size_t gr = i0 + row;
        g_S1[gr] = s1; g_S2[gr] = s2;
        g_E1p[gr] = expf(s1);  g_E1n[gr] = expf(0.2f * s1);
        float ep = expf(s2), en = expf(0.2f * s2);
        g_E2p[gr] = ep; g_E2n[gr] = en;
        e2ps[row] = ep; e2ns[row] = en;
    }
    __syncthreads();

    uint32_t* xt = (uint32_t*)(dynG + XT_OFF);
    unsigned short* dsts[4] = {g_X1h, g_X1l, g_X2h, g_X2l};

#pragma unroll 1
    for (int arr = 0; arr < 4; arr++) {
        const bool isX1 = (arr < 2);
        const bool isHi = ((arr & 1) == 0);
#pragma unroll
        for (int mt = 0; mt < 2; mt++) {
            int ra = r0 + 16 * mt;
            float sa = isX1 ? e2ps[ra] : e2ns[ra];
            float sb = isX1 ? e2ps[ra + 8] : e2ns[ra + 8];
#pragma unroll
            for (int n8 = 0; n8 < 8; n8++) {
                int wcol = cb / 2 + 4 * n8;
                uint32_t hi, lo;
                split2(dacc[mt][n8][0] * sa, dacc[mt][n8][1] * sa, hi, lo);
                xt[ra * XT_STRIDE + wcol] = isHi ? hi : lo;
                split2(dacc[mt][n8][2] * sb, dacc[mt][n8][3] * sb, hi, lo);
                xt[(ra + 8) * XT_STRIDE + wcol] = isHi ? hi : lo;
            }
        }
        __syncthreads();
        unsigned short* dst = dsts[arr];
#pragma unroll
        for (int r = 0; r < 8; r++) {
            int idx = tid + r * 512;
            int row = idx >> 5;
            int c4 = (idx & 31) * 4;
            uint32_t w0 = xt[row * XT_STRIDE + c4];
            uint32_t w1 = xt[row * XT_STRIDE + c4 + 1];
            uint32_t w2 = xt[row * XT_STRIDE + c4 + 2];
            uint32_t w3 = xt[row * XT_STRIDE + c4 + 3];
            *(uint4*)&dst[(i0 + row) * 256 + c4 * 2] = make_uint4(w0, w1, w2, w3);
        }
        __syncthreads();
    }
}

// ---------------------------------------------------------------------------
// K2: packed bit masks + Z sums (R14-proven, PLAIN layout:
//     word k of a row = j in [k*32, k*32+32), bit = j%32)
// ---------------------------------------------------------------------------
__global__ __launch_bounds__(256) void mask_kernel(const float* __restrict__ adj) {
    int row = blockIdx.x * 8 + (threadIdx.x >> 5);
    int lane = threadIdx.x & 31;
    int b = row >> 11;
    const float* ar = adj + (size_t)row * Nn;
    const float* s2g  = g_S2  + b * Nn;
    const float* epg = g_E2p + b * Nn;
    const float* eng = g_E2n + b * Nn;
    float ns1 = -g_S1[row];
    float z1 = 0.f, z2 = 0.f;
    uint32_t w1lo = 0, w1hi = 0, w2lo = 0, w2hi = 0;
#pragma unroll 4
    for (int k = 0; k < 64; k++) {
        int j = k * 32 + lane;
        bool on = ar[j] > 0.5f;
        bool pos = s2g[j] > ns1;
        bool m1 = on && pos, m2 = on && !pos;
        uint32_t b1 = __ballot_sync(0xffffffffu, m1);
        uint32_t b2 = __ballot_sync(0xffffffffu, m2);
        if (m1) z1 += epg[j];
        if (m2) z2 += eng[j];
        if ((k & 31) == lane) {
            if (k < 32) { w1lo = b1; w2lo = b2; }
            else        { w1hi = b1; w2hi = b2; }
        }
    }
#pragma unroll
    for (int o = 16; o; o >>= 1) {
        z1 += __shfl_xor_sync(0xffffffffu, z1, o);
        z2 += __shfl_xor_sync(0xffffffffu, z2, o);
    }
    g_M1[(size_t)row * 64 + lane] = w1lo;
    g_M1[(size_t)row * 64 + 32 + lane] = w1hi;
    g_M2[(size_t)row * 64 + lane] = w2lo;
    g_M2[(size_t)row * 64 + 32 + lane] = w2hi;
    if (lane == 0) { g_Z1[row] = z1; g_Z2[row] = z2; }
}

// ---------------------------------------------------------------------------
// K3: HMMA masked attention + LayerNorm + exact GELU, KC=64
//     2 X slots (64KB each), 2 mask buffers, 1-ahead pipeline
// ---------------------------------------------------------------------------
#define ROWS 128
#define XS_STRIDE 260
#define SLOT_BYTES 65536
#define MEXP0 (2 * SLOT_BYTES)              // 131072
#define MSTRIDE 144
#define MEXP1 (MEXP0 + ROWS * MSTRIDE)      // 149504
#define PACKED_OFF (MEXP1 + ROWS * MSTRIDE) // 167936
#define DYN_B (PACKED_OFF + 32768)          // 200704

__global__ void __launch_bounds__(512, 1)
attn_mma_kernel(const float* __restrict__ gamma, const float* __restrict__ beta,
                float* __restrict__ out) {
    extern __shared__ char dyn[];
    __shared__ float e1p_s[ROWS], e1n_s[ROWS], invz_s[ROWS], mu_s[ROWS], rs_s[ROWS];

    const int tid = threadIdx.x;
    const int lane = tid & 31;
    const int wid = tid >> 5;
    const int wm = wid >> 2, wn = wid & 3;
    const int b = blockIdx.y;
    const int i0 = blockIdx.x * ROWS;

    const uint32_t smem = smem_u32(dyn);
    float* xs = (float*)dyn;
    uint32_t* packed_s = (uint32_t*)(dyn + PACKED_OFF);

    if (tid < ROWS) {
        float e1p = g_E1p[b * Nn + i0 + tid];
        float e1n = g_E1n[b * Nn + i0 + tid];
        e1p_s[tid] = e1p;
        e1n_s[tid] = e1n;
        invz_s[tid] = 1.f / (e1p * g_Z1[b * Nn + i0 + tid] +
                             e1n * g_Z2[b * Nn + i0 + tid]);
    }

    const uint32_t aRowOff = (uint32_t)((32 * wm + ((lane >> 3) & 1) * 8 + (lane & 7)) * MSTRIDE
                                        + (lane >> 4) * 16);
    const int jb = ((lane >> 3) & 1) * 8 + (lane & 7);
    const int ub = 8 * wn + (lane >> 4);
    const int jsw = jb & 7;

    const int mi = tid >> 2;        // 0..127
    const int mq = tid & 3;         // 16 j each
    const uint32_t mstRel = (uint32_t)(mi * MSTRIDE + mq * 32);

    const int r0 = 32 * wm + (lane >> 2);
    const int cb = 64 * wn + (lane & 3) * 2;
    float* gy = g_Wh + ((size_t)b * Nn + i0) * Fd;

    float dacc[2][8][4];

    // expand 16 mask bits -> 8 bf16x2 words, two STS128
    auto expand = [&](int cc, uint32_t buf) {
        uint32_t word = packed_s[mi * 64 + 2 * cc + (mq >> 1)];
        uint32_t bits = (word >> ((mq & 1) * 16)) & 0xFFFFu;
        uint32_t w[8];
#pragma unroll
        for (int k = 0; k < 8; k++)
            w[k] = ((bits >> (2 * k)) & 1u) * 0x3F80u +
                   ((bits >> (2 * k + 1)) & 1u) * 0x3F800000u;
        STS128(buf + mstRel, w[0], w[1], w[2], w[3]);
        STS128(buf + mstRel + 16, w[4], w[5], w[6], w[7]);
    };

    auto issue_chunk = [&](int cc, const unsigned short* srcH,
                           const unsigned short* srcL) {
        uint32_t dst = smem + (uint32_t)(cc & 1) * SLOT_BYTES;
        size_t grow = (size_t)(cc * KC) * Fd;
#pragma unroll
        for (int r = 0; r < 4; r++) {
            int e = tid + r * 512;
            int j = e >> 5, u = e & 31;
            uint32_t d = dst + j * 512 + ((u ^ (j & 7)) << 4);
            cp_async16(d, srcH + grow + (size_t)j * Fd + u * 8);
            cp_async16(d + 32768, srcL + grow + (size_t)j * Fd + u * 8);
        }
        cp_commit();
    };

#pragma unroll 1
    for (int pass = 0; pass < 2; pass++) {
        const unsigned short* srcH =
            (pass == 0 ? g_X1h : g_X2h) + (size_t)b * Nn * Fd;
        const unsigned short* srcL =
            (pass == 0 ? g_X1l : g_X2l) + (size_t)b * Nn * Fd;
        const uint32_t* gM =
            (pass == 0 ? g_M1 : g_M2) + (size_t)(b * Nn + i0) * 64;

#pragma unroll
        for (int mt = 0; mt < 2; mt++)
#pragma unroll
            for (int n8 = 0; n8 < 8; n8++)
#pragma unroll
                for (int k = 0; k < 4; k++) dacc[mt][n8][k] = 0.f;

        // load packed masks (8192 words)
#pragma unroll
        for (int r = 0; r < 4; r++) {
            int idx = tid + r * 512;
            *(uint4*)&packed_s[idx * 4] = ((const uint4*)gM)[idx];
        }

        issue_chunk(0, srcH, srcL);
        __syncthreads();          // packed masks visible
        expand(0, smem + MEXP0);

#pragma unroll 1
        for (int it = 0; it < NIT; it++) {
            cp_wait0();           // X(it) landed
            __syncthreads();      // X(it) + mask(it) visible; MMA(it-1) done

            if (it + 1 < NIT) issue_chunk(it + 1, srcH, srcL);

            const uint32_t xb = smem + (uint32_t)(it & 1) * SLOT_BYTES;
            const uint32_t mbuf = smem + ((it & 1) ? MEXP1 : MEXP0);
#pragma unroll
            for (int ks = 0; ks < 4; ks++) {
                uint32_t a0[4], a1[4];
                ldsm4(a0, mbuf + aRowOff + ks * 32);
                ldsm4(a1, mbuf + aRowOff + 16 * MSTRIDE + ks * 32);
                const int j = jb + ks * 16;
                const uint32_t rowb = xb + j * 512;
#pragma unroll
                for (int ng = 0; ng < 4; ng++) {
                    const int u = ub + 2 * ng;
                    const uint32_t addrH = rowb + ((u ^ jsw) << 4);
                    uint32_t bh[4], bl[4];
                    ldsm4t(bh, addrH);
                    ldsm4t(bl, addrH + 32768);
                    mma16816(dacc[0][2 * ng],     a0, bh[0], bh[1]);
                    mma16816(dacc[0][2 * ng + 1], a0, bh[2], bh[3]);
                    mma16816(dacc[1][2 * ng],     a1, bh[0], bh[1]);
                    mma16816(dacc[1][2 * ng + 1], a1, bh[2], bh[3]);
                    mma16816(dacc[0][2 * ng],     a0, bl[0], bl[1]);
                    mma16816(dacc[0][2 * ng + 1], a0, bl[2], bl[3]);
                    mma16816(dacc[1][2 * ng],     a1, bl[0], bl[1]);
                    mma16816(dacc[1][2 * ng + 1], a1, bl[2], bl[3]);
                }
            }

            if (it + 1 < NIT)
                expand(it + 1, smem + (((it + 1) & 1) ? MEXP1 : MEXP0));
        }
        __syncthreads();   // all MMA reads + expands done before pass flip

        if (pass == 0) {
#pragma unroll
            for (int mt = 0; mt < 2; mt++) {
                int ra = r0 + 16 * mt;
                float ea = e1p_s[ra], eb = e1p_s[ra + 8];
#pragma unroll
                for (int n8 = 0; n8 < 8; n8++) {
                    int c = cb + 8 * n8;
                    *(float2*)&gy[(size_t)ra * 256 + c] =
                        make_float2(ea * dacc[mt][n8][0], ea * dacc[mt][n8][1]);
                    *(float2*)&gy[(size_t)(ra + 8) * 256 + c] =
                        make_float2(eb * dacc[mt][n8][2], eb * dacc[mt][n8][3]);
                }
            }
        }
    }

    // combine: x = (gy + e1n*Y2) * invZ -> xs (overlays main-loop smem)
#pragma unroll
    for (int mt = 0; mt < 2; mt++) {
        int ra = r0 + 16 * mt;
        float ea = e1n_s[ra], eb = e1n_s[ra + 8];
        float iza = invz_s[ra], izb = invz_s[ra + 8];
#pragma unroll
        for (int n8 = 0; n8 < 8; n8++) {
            int c = cb + 8 * n8;
            float2 ya = *(const float2*)&gy[(size_t)ra * 256 + c];
            float2 yb = *(const float2*)&gy[(size_t)(ra + 8) * 256 + c];
            xs[ra * XS_STRIDE + c]     = (ya.x + ea * dacc[mt][n8][0]) * iza;
            xs[ra * XS_STRIDE + c + 1] = (ya.y + ea * dacc[mt][n8][1]) * iza;
            xs[(ra + 8) * XS_STRIDE + c]     = (yb.x + eb * dacc[mt][n8][2]) * izb;
            xs[(ra + 8) * XS_STRIDE + c + 1] = (yb.y + eb * dacc[mt][n8][3]) * izb;
        }
    }
    __syncthreads();

    // LayerNorm stats
    {
        int row = tid >> 2, q = tid & 3;
        const float4* xr = (const float4*)&xs[row * XS_STRIDE + q * 64];
        float sum = 0.f, ssq = 0.f;
#pragma unroll
        for (int k = 0; k < 16; k++) {
            float4 v = xr[k];
            sum += v.x + v.y + v.z + v.w;
            ssq += v.x * v.x + v.y * v.y + v.z * v.z + v.w * v.w;
        }
        sum += __shfl_xor_sync(0xffffffffu, sum, 1);
        sum += __shfl_xor_sync(0xffffffffu, sum, 2);
        ssq += __shfl_xor_sync(0xffffffffu, ssq, 1);
        ssq += __shfl_xor_sync(0xffffffffu, ssq, 2);
        if (q == 0) {
            float mu = sum * (1.f / 256.f);
            float var = fmaxf(ssq * (1.f / 256.f) - mu * mu, 0.f);
            mu_s[row] = mu;
            rs_s[row] = rsqrtf(var + 1e-5f);
        }
    }
    __syncthreads();

    // gamma/beta + exact GELU, coalesced store
    float* outb = out + ((size_t)b * Nn + i0) * Fd;
#pragma unroll 1
    for (int r = 0; r < 16; r++) {
        int u = tid + r * 512;
        int i = u >> 6;
        int c4 = (u & 63) * 4;
        float mu = mu_s[i], rs = rs_s[i];
        float4 xv = *(const float4*)&xs[i * XS_STRIDE + c4];
        float4 g = *(const float4*)&gamma[c4];
        float4 be = *(const float4*)&beta[c4];
        float x[4] = {xv.x, xv.y, xv.z, xv.w};
        float gv[4] = {g.x, g.y, g.z, g.w};
        float bv[4] = {be.x, be.y, be.z, be.w};
        float ov[4];
#pragma unroll
        for (int e = 0; e < 4; e++) {
            float y = (x[e] - mu) * rs * gv[e] + bv[e];
            ov[e] = 0.5f * y * (1.f + erff(y * 0.7071067811865475f));
        }
        *(float4*)&outb[(size_t)i * 256 + c4] = make_float4(ov[0], ov[1], ov[2], ov[3]);
    }
}

// ---------------------------------------------------------------------------
extern "C" void kernel_launch(void* const* d_in, const int* in_sizes, int n_in,
                              void* d_out, int out_size) {
    const float* h     = (const float*)d_in[0];
    const float* adj   = (const float*)d_in[1];
    const float* W     = (const float*)d_in[2];
    const float* a     = (const float*)d_in[3];
    const float* gamma = (const float*)d_in[4];
    const float* beta  = (const float*)d_in[5];
    float* out = (float*)d_out;

    cudaFuncSetAttribute(gemm1_kernel,
                         cudaFuncAttributeMaxDynamicSharedMemorySize, G1_DYN);
    cudaFuncSetAttribute(attn_mma_kernel,
                         cudaFuncAttributeMaxDynamicSharedMemorySize, DYN_B);

    gemm1_kernel<<<128, 512, G1_DYN>>>(h, W, a);
    mask_kernel<<<2048, 256>>>(adj);
    attn_mma_kernel<<<dim3(16, 8), 512, DYN_B>>>(gamma, beta, out);
}